// round 13
// baseline (speedup 1.0000x reference)
#include <cuda_runtime.h>
#include <cuda_fp16.h>
#include <cstdint>

#define BATCH 16
#define CCH   256
#define NPIX  1024

// ---------------- scratch (static device globals; no allocation) ----------------
__device__ __align__(128) __half g_xnT[BATCH * NPIX * CCH];           //  8 MB [b][n][c]
__device__ __align__(128) __half g_qkT[BATCH * NPIX * 3 * CCH];       // 24 MB [b][n][o] q|k|v
__device__ __align__(128) __half g_E  [(size_t)BATCH * NPIX * NPIX];  // 32 MB [b][n][m]
__device__ __align__(128) __half g_O  [BATCH * NPIX * CCH];           //  8 MB [b][n][c]
__device__ __align__(128) float  g_rs [BATCH * NPIX];
__device__ __align__(128) __half g_wq [3 * CCH * CCH];
__device__ __align__(128) __half g_wp [CCH * CCH];

// ---------------- helpers ----------------
__device__ __forceinline__ void cpa16(uint32_t dst, const void* src) {
    asm volatile("cp.async.cg.shared.global [%0], [%1], 16;" :: "r"(dst), "l"(src));
}
__device__ __forceinline__ void cp_commit() { asm volatile("cp.async.commit_group;"); }
template<int N> __device__ __forceinline__ void cp_wait() { asm volatile("cp.async.wait_group %0;" :: "n"(N)); }

__device__ __forceinline__ void mma_f16(float& c0, float& c1, float& c2, float& c3,
                                        uint32_t a0, uint32_t a1, uint32_t a2, uint32_t a3,
                                        uint32_t b0, uint32_t b1) {
    asm volatile(
        "mma.sync.aligned.m16n8k16.row.col.f32.f16.f16.f32 "
        "{%0,%1,%2,%3}, {%4,%5,%6,%7}, {%8,%9}, {%0,%1,%2,%3};"
        : "+f"(c0), "+f"(c1), "+f"(c2), "+f"(c3)
        : "r"(a0), "r"(a1), "r"(a2), "r"(a3), "r"(b0), "r"(b1));
}
__device__ __forceinline__ void ldsm4(uint32_t& r0, uint32_t& r1, uint32_t& r2, uint32_t& r3, uint32_t a) {
    asm volatile("ldmatrix.sync.aligned.m8n8.x4.shared.b16 {%0,%1,%2,%3}, [%4];"
        : "=r"(r0), "=r"(r1), "=r"(r2), "=r"(r3) : "r"(a));
}
__device__ __forceinline__ void ldsm4t(uint32_t& r0, uint32_t& r1, uint32_t& r2, uint32_t& r3, uint32_t a) {
    asm volatile("ldmatrix.sync.aligned.m8n8.x4.trans.shared.b16 {%0,%1,%2,%3}, [%4];"
        : "=r"(r0), "=r"(r1), "=r"(r2), "=r"(r3) : "r"(a));
}

// ---------------- GroupNorm (+ fused weight convert + rowsum zero) ----------------
__global__ void groupnorm_k(const float* __restrict__ x, const float* __restrict__ gamma,
                            const float* __restrict__ beta, __half* __restrict__ xnT,
                            const float* __restrict__ wqf, const float* __restrict__ wpf,
                            __half* __restrict__ owq, __half* __restrict__ owp,
                            float* __restrict__ rs)
{
    __shared__ float smT[32][65];
    __shared__ float red0[8], red1[8];
    const int bg = blockIdx.x, b = bg >> 3, g = bg & 7;
    const float* xp = x + (size_t)bg * 32768;
    const int tid = threadIdx.x, lane = tid & 31, warp = tid >> 5;

    // fused prep (grid-strided over all 128*256 = 32768 threads)
    {
        int gi = bg * 256 + tid;
        #pragma unroll
        for (int j = 0; j < 6; j++) {
            int idx = gi + 32768 * j;
            if (idx < 3 * CCH * CCH) owq[idx] = __float2half(wqf[idx]);
        }
        #pragma unroll
        for (int j = 0; j < 2; j++) {
            int idx = gi + 32768 * j;
            if (idx < CCH * CCH) owp[idx] = __float2half(wpf[idx]);
        }
        if (gi < BATCH * NPIX) rs[gi] = 0.f;
    }

    float s = 0.f, s2 = 0.f;
    for (int i = tid; i < 32768; i += 256) { float v = xp[i]; s += v; s2 += v * v; }
    #pragma unroll
    for (int o = 16; o > 0; o >>= 1) {
        s  += __shfl_xor_sync(0xffffffffu, s,  o);
        s2 += __shfl_xor_sync(0xffffffffu, s2, o);
    }
    if (lane == 0) { red0[warp] = s; red1[warp] = s2; }
    __syncthreads();
    if (warp == 0) {
        s  = (lane < 8) ? red0[lane] : 0.f;
        s2 = (lane < 8) ? red1[lane] : 0.f;
        #pragma unroll
        for (int o = 4; o > 0; o >>= 1) {
            s  += __shfl_xor_sync(0xffffffffu, s,  o);
            s2 += __shfl_xor_sync(0xffffffffu, s2, o);
        }
        if (lane == 0) { red0[0] = s; red1[0] = s2; }
    }
    __syncthreads();
    float mean = red0[0] * (1.f / 32768.f);
    float var  = red1[0] * (1.f / 32768.f) - mean * mean;
    float rstd = rsqrtf(var + 1e-5f);

    const int p = tid >> 2, cq = (tid & 3) * 8;
    float gm[8], bt[8];
    #pragma unroll
    for (int j = 0; j < 8; j++) {
        float gj = gamma[g * 32 + cq + j] * rstd;
        gm[j] = gj;
        bt[j] = beta[g * 32 + cq + j] - mean * gj;
    }
    for (int tp = 0; tp < 1024; tp += 64) {
        __syncthreads();
        #pragma unroll
        for (int i = 0; i < 8; i++) {
            int idx = tid + 256 * i;
            int c = idx >> 6, pp = idx & 63;
            smT[c][pp] = xp[c * 1024 + tp + pp];
        }
        __syncthreads();
        uint32_t pk[4];
        #pragma unroll
        for (int j = 0; j < 4; j++) {
            float v0 = smT[cq + 2 * j][p]     * gm[2 * j]     + bt[2 * j];
            float v1 = smT[cq + 2 * j + 1][p] * gm[2 * j + 1] + bt[2 * j + 1];
            __half2 h = __floats2half2_rn(v0, v1);
            pk[j] = *(uint32_t*)&h;
        }
        *(uint4*)&xnT[((size_t)b * NPIX + tp + p) * CCH + g * 32 + cq] = *(uint4*)pk;
    }
}

// ---------------- persistent FP16 tensor-core GEMM, CTA 128x128, warp 64x32, BK=64 ----------------
// D[m,n] = sum_k A[m,k] * B(n,k)   (TRB=0: B row-n k-major, stride ldb)
//                                  (TRB=1: B stored [k][n], row stride ldb)
// EPI: 0 = +bias[col] -> fp16 ; 1 = exp(alpha*d)+rowsum atomic -> fp16 ;
//      2 = d/rowsum[row] -> fp16 ; 3 = d + bias[row] + resid -> fp32
// 256 threads (8 warps 2x4), 3-stage cp.async ring over a flat slab stream
// spanning all tiles assigned to this CTA — the pipeline never drains.
#define A_STG  18432   // 128 rows * 144 B
#define B0_STG 18432
#define B1_STG 17408   // 64 rows * 272 B
#define B_OFF  55296   // 3 * A_STG
#define SMEM_SZ (B_OFF + 3 * B0_STG)   // 110592 B

template<int EPI, int TRB>
__global__ void __launch_bounds__(256, 2)
gemm_h(const __half* __restrict__ A, const __half* __restrict__ B,
       void* __restrict__ Cv, int K, int lda, int ldb, int ldc,
       long sA, long sB, long sC,
       const float* __restrict__ bias, const float* __restrict__ resid, long sR,
       float* __restrict__ rowsum, float alpha,
       int ntx, int nty, int ntz)
{
    extern __shared__ char dsh[];
    const uint32_t sb = (uint32_t)__cvta_generic_to_shared(dsh);
    const uint32_t AsB = sb;
    const uint32_t BsB = sb + B_OFF;

    const int tid = threadIdx.x, lane = tid & 31, wid = tid >> 5;
    const int wm = wid & 1, wn = wid >> 1;
    const int g = lane >> 2, tr = lane & 3;

    const int a_row = (lane & 7) | (((lane >> 3) & 1) << 3);
    const int a_hi4 = (lane >= 16) ? 4 : 0;
    const int b_row = (lane & 7) + ((lane >= 16) ? 8 : 0);
    const int b_hi4 = ((lane >> 3) & 1) ? 4 : 0;
    const int t_row = lane & 15, t_col = (lane >> 4) * 8;

    const uint32_t aBase  = AsB + (uint32_t)((wm * 64 + a_row) * 144 + a_hi4 * 4);
    const uint32_t bBase0 = BsB + (uint32_t)((wn * 32 + b_row) * 144 + b_hi4 * 4);
    const uint32_t bBase1 = BsB + (uint32_t)(t_row * 272 + (wn * 32 + t_col) * 2);

    const int kt = K >> 6;
    const int ntiles = ntx * nty * ntz;
    const int G = gridDim.x;
    const int mycount = (ntiles - blockIdx.x + G - 1) / G;
    const int nslabs = mycount * kt;

    // issue all cp.asyncs for slab j (tile = bid + (j/kt)*G, k0 = (j%kt)*64, stage = j%3)
    auto issue_slab = [&](int j) {
        const int T = blockIdx.x + (j / kt) * G;
        const int xx = T % ntx;
        const int rest = T / ntx;
        const int yy = rest % nty;
        const int zz = rest / nty;
        const int k0 = (j % kt) * 64;
        const int s = j % 3;
        const __half* Ap = A + (size_t)zz * sA + (size_t)(yy * 128) * lda;
        const __half* Bp = B + (size_t)zz * sB;
        #pragma unroll
        for (int p = 0; p < 4; p++) {
            int idx = tid + 256 * p;
            int row = idx >> 3, ch = idx & 7;
            cpa16(AsB + s * A_STG + row * 144 + ch * 16,
                  Ap + (size_t)row * lda + k0 + ch * 8);
        }
        if (TRB == 0) {
            #pragma unroll
            for (int p = 0; p < 4; p++) {
                int idx = tid + 256 * p;
                int row = idx >> 3, ch = idx & 7;
                cpa16(BsB + s * B0_STG + row * 144 + ch * 16,
                      Bp + (size_t)(xx * 128 + row) * ldb + k0 + ch * 8);
            }
        } else {
            #pragma unroll
            for (int p = 0; p < 4; p++) {
                int idx = tid + 256 * p;
                int krow = idx >> 4, kch = idx & 15;
                cpa16(BsB + s * B1_STG + krow * 272 + kch * 16,
                      Bp + (size_t)(k0 + krow) * ldb + xx * 128 + kch * 8);
            }
        }
        cp_commit();
    };

    float c[4][4][4];
    int cm0 = 0, cn0 = 0, cz = 0;

    issue_slab(0);
    if (1 < nslabs) issue_slab(1);

    for (int j = 0; j < nslabs; j++) {
        if (j + 1 < nslabs) cp_wait<1>(); else cp_wait<0>();
        __syncthreads();

        if ((j % kt) == 0) {
            const int T = blockIdx.x + (j / kt) * G;
            const int xx = T % ntx;
            const int rest = T / ntx;
            cm0 = (rest % nty) * 128; cn0 = xx * 128; cz = rest / nty;
            #pragma unroll
            for (int i = 0; i < 4; i++)
                #pragma unroll
                for (int jj = 0; jj < 4; jj++)
                    #pragma unroll
                    for (int t = 0; t < 4; t++) c[i][jj][t] = 0.f;
        }

        const int s = j % 3;
        #pragma unroll
        for (int kk = 0; kk < 4; kk++) {
            uint32_t a[4][4];
            #pragma unroll
            for (int mf = 0; mf < 4; mf++)
                ldsm4(a[mf][0], a[mf][1], a[mf][2], a[mf][3],
                      aBase + s * A_STG + mf * 2304 + kk * 32);
            uint32_t bf[4][2];
            #pragma unroll
            for (int nf2 = 0; nf2 < 2; nf2++) {
                uint32_t r0, r1, r2, r3;
                if (TRB == 0) {
                    ldsm4(r0, r1, r2, r3, bBase0 + s * B0_STG + nf2 * 2304 + kk * 32);
                } else {
                    ldsm4t(r0, r1, r2, r3, bBase1 + s * B1_STG + kk * 4352 + nf2 * 32);
                }
                bf[nf2 * 2][0] = r0; bf[nf2 * 2][1] = r1;
                bf[nf2 * 2 + 1][0] = r2; bf[nf2 * 2 + 1][1] = r3;
            }
            #pragma unroll
            for (int mf = 0; mf < 4; mf++)
                #pragma unroll
                for (int nf = 0; nf < 4; nf++)
                    mma_f16(c[mf][nf][0], c[mf][nf][1], c[mf][nf][2], c[mf][nf][3],
                            a[mf][0], a[mf][1], a[mf][2], a[mf][3],
                            bf[nf][0], bf[nf][1]);
        }

        if (j + 2 < nslabs) issue_slab(j + 2);   // keeps pipeline full across tile boundaries

        if ((j % kt) == kt - 1) {
            // ---------------- epilogue (overlaps next tile's loads) ----------------
            #pragma unroll
            for (int mf = 0; mf < 4; mf++) {
                const int r0 = cm0 + wm * 64 + mf * 16 + g;
                const int r1 = r0 + 8;
                float add0 = 0.f, add1 = 0.f, mul0 = 1.f, mul1 = 1.f;
                if (EPI == 3) { add0 = bias[r0]; add1 = bias[r1]; }
                if (EPI == 2) {
                    mul0 = 1.f / rowsum[cz * NPIX + r0];
                    mul1 = 1.f / rowsum[cz * NPIX + r1];
                }
                float rsum0 = 0.f, rsum1 = 0.f;
                #pragma unroll
                for (int nf = 0; nf < 4; nf++) {
                    const int cc = cn0 + wn * 32 + nf * 8 + 2 * tr;
                    float v0 = c[mf][nf][0], v1 = c[mf][nf][1];
                    float v2 = c[mf][nf][2], v3 = c[mf][nf][3];
                    if (EPI == 0) {
                        v0 += bias[cc]; v1 += bias[cc + 1];
                        v2 += bias[cc]; v3 += bias[cc + 1];
                    }
                    if (EPI == 1) {
                        v0 = __expf(v0 * alpha); v1 = __expf(v1 * alpha);
                        v2 = __expf(v2 * alpha); v3 = __expf(v3 * alpha);
                        rsum0 += v0 + v1; rsum1 += v2 + v3;
                    }
                    if (EPI == 2) { v0 *= mul0; v1 *= mul0; v2 *= mul1; v3 *= mul1; }
                    if (EPI != 3) {
                        __half* Ch = (__half*)Cv + (size_t)cz * sC;
                        *(__half2*)&Ch[(size_t)r0 * ldc + cc] = __floats2half2_rn(v0, v1);
                        *(__half2*)&Ch[(size_t)r1 * ldc + cc] = __floats2half2_rn(v2, v3);
                    } else {
                        float* Cf = (float*)Cv + (size_t)cz * sC;
                        const float* Rp = resid + (size_t)cz * sR;
                        float2 o0 = make_float2(v0 + add0 + Rp[(size_t)r0 * ldc + cc],
                                                v1 + add0 + Rp[(size_t)r0 * ldc + cc + 1]);
                        float2 o1 = make_float2(v2 + add1 + Rp[(size_t)r1 * ldc + cc],
                                                v3 + add1 + Rp[(size_t)r1 * ldc + cc + 1]);
                        *(float2*)&Cf[(size_t)r0 * ldc + cc] = o0;
                        *(float2*)&Cf[(size_t)r1 * ldc + cc] = o1;
                    }
                }
                if (EPI == 1) {
                    rsum0 += __shfl_xor_sync(0xffffffffu, rsum0, 1);
                    rsum0 += __shfl_xor_sync(0xffffffffu, rsum0, 2);
                    rsum1 += __shfl_xor_sync(0xffffffffu, rsum1, 1);
                    rsum1 += __shfl_xor_sync(0xffffffffu, rsum1, 2);
                    if (tr == 0) {
                        atomicAdd(&rowsum[cz * NPIX + r0], rsum0);
                        atomicAdd(&rowsum[cz * NPIX + r1], rsum1);
                    }
                }
            }
        }
    }
}

// ---------------- launch ----------------
static inline int pgrid(int tiles) { return tiles < 296 ? tiles : 296; }

extern "C" void kernel_launch(void* const* d_in, const int* in_sizes, int n_in,
                              void* d_out, int out_size)
{
    const float* x      = (const float*)d_in[0];
    const float* gamma  = (const float*)d_in[1];
    const float* beta   = (const float*)d_in[2];
    const float* w_qkv  = (const float*)d_in[3];
    const float* b_qkv  = (const float*)d_in[4];
    const float* w_proj = (const float*)d_in[5];
    const float* b_proj = (const float*)d_in[6];
    float* out = (float*)d_out;

    __half *xnT, *qkT, *E, *O, *wq, *wp;
    float* rs;
    cudaGetSymbolAddress((void**)&xnT, g_xnT);
    cudaGetSymbolAddress((void**)&qkT, g_qkT);
    cudaGetSymbolAddress((void**)&E,   g_E);
    cudaGetSymbolAddress((void**)&O,   g_O);
    cudaGetSymbolAddress((void**)&wq,  g_wq);
    cudaGetSymbolAddress((void**)&wp,  g_wp);
    cudaGetSymbolAddress((void**)&rs,  g_rs);

    cudaFuncSetAttribute(gemm_h<0,0>, cudaFuncAttributeMaxDynamicSharedMemorySize, SMEM_SZ);
    cudaFuncSetAttribute(gemm_h<1,0>, cudaFuncAttributeMaxDynamicSharedMemorySize, SMEM_SZ);
    cudaFuncSetAttribute(gemm_h<2,1>, cudaFuncAttributeMaxDynamicSharedMemorySize, SMEM_SZ);
    cudaFuncSetAttribute(gemm_h<3,0>, cudaFuncAttributeMaxDynamicSharedMemorySize, SMEM_SZ);

    // 1) GroupNorm (+weights->fp16, rowsum=0)
    groupnorm_k<<<BATCH * 8, 256>>>(x, gamma, beta, xnT, w_qkv, w_proj, wq, wp, rs);

    // 2) QKV: qkT[n][o] = sum_c xnT[n,c]*Wqkv[o,c] + b[o]   tiles 6x8x16
    gemm_h<0,0><<<pgrid(6 * 8 * BATCH), 256, SMEM_SZ>>>(
        xnT, wq, qkT, CCH, CCH, CCH, 768,
        (long)NPIX * CCH, 0L, (long)NPIX * 768,
        b_qkv, nullptr, 0L, nullptr, 0.f, 6, 8, BATCH);

    // 3) scores+exp+rowsum: E[n,m] = exp((1/16) sum_c q[n,c]*k[m,c])   tiles 8x8x16
    gemm_h<1,0><<<pgrid(8 * 8 * BATCH), 256, SMEM_SZ>>>(
        qkT, qkT + CCH, E, CCH, 768, 768, NPIX,
        (long)NPIX * 768, (long)NPIX * 768, (long)NPIX * NPIX,
        nullptr, nullptr, 0L, rs, 0.0625f, 8, 8, BATCH);

    // 4) AV + normalize: O[n,c] = (sum_m E[n,m]*V[m,c]) / rowsum[n]   tiles 2x8x16
    gemm_h<2,1><<<pgrid(2 * 8 * BATCH), 256, SMEM_SZ>>>(
        E, qkT + 512, O, NPIX, NPIX, 768, CCH,
        (long)NPIX * NPIX, (long)NPIX * 768, (long)NPIX * CCH,
        nullptr, nullptr, 0L, rs, 1.f, 2, 8, BATCH);

    // 5) proj + bias + residual   tiles 8x2x16
    gemm_h<3,0><<<pgrid(8 * 2 * BATCH), 256, SMEM_SZ>>>(
        wp, O, out, CCH, CCH, CCH, NPIX,
        0L, (long)NPIX * CCH, (long)CCH * NPIX,
        b_proj, x, (long)CCH * NPIX, nullptr, 1.f, 8, 2, BATCH);
}

// round 14
// speedup vs baseline: 1.0503x; 1.0503x over previous
#include <cuda_runtime.h>
#include <cuda_fp16.h>
#include <cstdint>

#define BATCH 16
#define CCH   256
#define NPIX  1024

// ---------------- scratch (static device globals; no allocation) ----------------
__device__ __align__(128) __half g_xnT[BATCH * NPIX * CCH];           //  8 MB [b][n][c]
__device__ __align__(128) __half g_qkT[BATCH * NPIX * 3 * CCH];       // 24 MB [b][n][o] q|k|v
__device__ __align__(128) __half g_E  [(size_t)BATCH * NPIX * NPIX];  // 32 MB [b][n][m]
__device__ __align__(128) __half g_O  [BATCH * NPIX * CCH];           //  8 MB [b][n][c]
__device__ __align__(128) float  g_rs [BATCH * NPIX];
__device__ __align__(128) __half g_wq [3 * CCH * CCH];
__device__ __align__(128) __half g_wp [CCH * CCH];

// ---------------- helpers ----------------
__device__ __forceinline__ void cpa16(uint32_t dst, const void* src) {
    asm volatile("cp.async.cg.shared.global [%0], [%1], 16;" :: "r"(dst), "l"(src));
}
__device__ __forceinline__ void cp_commit() { asm volatile("cp.async.commit_group;"); }
template<int N> __device__ __forceinline__ void cp_wait() { asm volatile("cp.async.wait_group %0;" :: "n"(N)); }

__device__ __forceinline__ void mma_f16(float& c0, float& c1, float& c2, float& c3,
                                        uint32_t a0, uint32_t a1, uint32_t a2, uint32_t a3,
                                        uint32_t b0, uint32_t b1) {
    asm volatile(
        "mma.sync.aligned.m16n8k16.row.col.f32.f16.f16.f32 "
        "{%0,%1,%2,%3}, {%4,%5,%6,%7}, {%8,%9}, {%0,%1,%2,%3};"
        : "+f"(c0), "+f"(c1), "+f"(c2), "+f"(c3)
        : "r"(a0), "r"(a1), "r"(a2), "r"(a3), "r"(b0), "r"(b1));
}
__device__ __forceinline__ void ldsm4(uint32_t& r0, uint32_t& r1, uint32_t& r2, uint32_t& r3, uint32_t a) {
    asm volatile("ldmatrix.sync.aligned.m8n8.x4.shared.b16 {%0,%1,%2,%3}, [%4];"
        : "=r"(r0), "=r"(r1), "=r"(r2), "=r"(r3) : "r"(a));
}
__device__ __forceinline__ void ldsm4t(uint32_t& r0, uint32_t& r1, uint32_t& r2, uint32_t& r3, uint32_t a) {
    asm volatile("ldmatrix.sync.aligned.m8n8.x4.trans.shared.b16 {%0,%1,%2,%3}, [%4];"
        : "=r"(r0), "=r"(r1), "=r"(r2), "=r"(r3) : "r"(a));
}

// ---------------- GroupNorm (+ fused weight convert + rowsum zero) ----------------
__global__ void groupnorm_k(const float* __restrict__ x, const float* __restrict__ gamma,
                            const float* __restrict__ beta, __half* __restrict__ xnT,
                            const float* __restrict__ wqf, const float* __restrict__ wpf,
                            __half* __restrict__ owq, __half* __restrict__ owp,
                            float* __restrict__ rs)
{
    __shared__ float smT[32][65];
    __shared__ float red0[8], red1[8];
    const int bg = blockIdx.x, b = bg >> 3, g = bg & 7;
    const float* xp = x + (size_t)bg * 32768;
    const int tid = threadIdx.x, lane = tid & 31, warp = tid >> 5;

    // fused prep (grid-strided over all 128*256 = 32768 threads)
    {
        int gi = bg * 256 + tid;
        #pragma unroll
        for (int j = 0; j < 6; j++) {
            int idx = gi + 32768 * j;
            if (idx < 3 * CCH * CCH) owq[idx] = __float2half(wqf[idx]);
        }
        #pragma unroll
        for (int j = 0; j < 2; j++) {
            int idx = gi + 32768 * j;
            if (idx < CCH * CCH) owp[idx] = __float2half(wpf[idx]);
        }
        if (gi < BATCH * NPIX) rs[gi] = 0.f;
    }

    float s = 0.f, s2 = 0.f;
    for (int i = tid; i < 32768; i += 256) { float v = xp[i]; s += v; s2 += v * v; }
    #pragma unroll
    for (int o = 16; o > 0; o >>= 1) {
        s  += __shfl_xor_sync(0xffffffffu, s,  o);
        s2 += __shfl_xor_sync(0xffffffffu, s2, o);
    }
    if (lane == 0) { red0[warp] = s; red1[warp] = s2; }
    __syncthreads();
    if (warp == 0) {
        s  = (lane < 8) ? red0[lane] : 0.f;
        s2 = (lane < 8) ? red1[lane] : 0.f;
        #pragma unroll
        for (int o = 4; o > 0; o >>= 1) {
            s  += __shfl_xor_sync(0xffffffffu, s,  o);
            s2 += __shfl_xor_sync(0xffffffffu, s2, o);
        }
        if (lane == 0) { red0[0] = s; red1[0] = s2; }
    }
    __syncthreads();
    float mean = red0[0] * (1.f / 32768.f);
    float var  = red1[0] * (1.f / 32768.f) - mean * mean;
    float rstd = rsqrtf(var + 1e-5f);

    const int p = tid >> 2, cq = (tid & 3) * 8;
    float gm[8], bt[8];
    #pragma unroll
    for (int j = 0; j < 8; j++) {
        float gj = gamma[g * 32 + cq + j] * rstd;
        gm[j] = gj;
        bt[j] = beta[g * 32 + cq + j] - mean * gj;
    }
    for (int tp = 0; tp < 1024; tp += 64) {
        __syncthreads();
        #pragma unroll
        for (int i = 0; i < 8; i++) {
            int idx = tid + 256 * i;
            int c = idx >> 6, pp = idx & 63;
            smT[c][pp] = xp[c * 1024 + tp + pp];
        }
        __syncthreads();
        uint32_t pk[4];
        #pragma unroll
        for (int j = 0; j < 4; j++) {
            float v0 = smT[cq + 2 * j][p]     * gm[2 * j]     + bt[2 * j];
            float v1 = smT[cq + 2 * j + 1][p] * gm[2 * j + 1] + bt[2 * j + 1];
            __half2 h = __floats2half2_rn(v0, v1);
            pk[j] = *(uint32_t*)&h;
        }
        *(uint4*)&xnT[((size_t)b * NPIX + tp + p) * CCH + g * 32 + cq] = *(uint4*)pk;
    }
}

// ---------------- FP16 tensor-core GEMM, CTA 128x128, warp 64x32, BK=64, 3-stage ----------------
// D[m,n] = sum_k A[m,k] * B(n,k)   (TRB=0: B row-n k-major, stride ldb)
//                                  (TRB=1: B stored [k][n], row stride ldb)
// EPI: 0 = +bias[col] -> fp16 ; 1 = exp(alpha*d)+rowsum atomic -> fp16 ;
//      2 = d/rowsum[row] -> fp16 ; 3 = d + bias[row] + resid -> fp32
// 256 threads (8 warps 2x4), BK=64, 3-stage cp.async ring, ONE barrier per slab,
// next-slab loads issued immediately after the barrier (max lead time).
#define A_STG  18432   // 128 rows * 144 B
#define B0_STG 18432
#define B1_STG 17408   // 64 rows * 272 B
#define B_OFF  55296   // 3 * A_STG
#define SMEM_SZ (B_OFF + 3 * B0_STG)   // 110592 B

template<int EPI, int TRB>
__global__ void __launch_bounds__(256, 2)
gemm_h(const __half* __restrict__ A, const __half* __restrict__ B,
       void* __restrict__ Cv, int K, int lda, int ldb, int ldc,
       long sA, long sB, long sC,
       const float* __restrict__ bias, const float* __restrict__ resid, long sR,
       float* __restrict__ rowsum, float alpha)
{
    extern __shared__ char dsh[];
    const uint32_t sb = (uint32_t)__cvta_generic_to_shared(dsh);
    const uint32_t AsB = sb;
    const uint32_t BsB = sb + B_OFF;

    const int z = blockIdx.z;
    A += (size_t)z * sA;
    B += (size_t)z * sB;

    const int m0 = blockIdx.y * 128, n0 = blockIdx.x * 128;
    const int tid = threadIdx.x, lane = tid & 31, wid = tid >> 5;
    const int wm = wid & 1, wn = wid >> 1;   // 2 x 4 warps, warp tile 64x32
    const int g = lane >> 2, tr = lane & 3;

    const int a_row = (lane & 7) | (((lane >> 3) & 1) << 3);
    const int a_hi4 = (lane >= 16) ? 4 : 0;
    const int b_row = (lane & 7) + ((lane >= 16) ? 8 : 0);
    const int b_hi4 = ((lane >> 3) & 1) ? 4 : 0;
    const int t_row = lane & 15, t_col = (lane >> 4) * 8;

    const uint32_t aBase  = AsB + (uint32_t)((wm * 64 + a_row) * 144 + a_hi4 * 4);
    const uint32_t bBase0 = BsB + (uint32_t)((wn * 32 + b_row) * 144 + b_hi4 * 4);
    const uint32_t bBase1 = BsB + (uint32_t)(t_row * 272 + (wn * 32 + t_col) * 2);

    float c[4][4][4];
    #pragma unroll
    for (int i = 0; i < 4; i++)
        #pragma unroll
        for (int j = 0; j < 4; j++)
            #pragma unroll
            for (int t = 0; t < 4; t++) c[i][j][t] = 0.f;

    auto loadA = [&](int s, int k0) {
        #pragma unroll
        for (int p = 0; p < 4; p++) {
            int idx = tid + 256 * p;
            int row = idx >> 3, ch = idx & 7;
            cpa16(AsB + s * A_STG + row * 144 + ch * 16,
                  A + (size_t)(m0 + row) * lda + k0 + ch * 8);
        }
    };
    auto loadB = [&](int s, int k0) {
        if (TRB == 0) {
            #pragma unroll
            for (int p = 0; p < 4; p++) {
                int idx = tid + 256 * p;
                int row = idx >> 3, ch = idx & 7;
                cpa16(BsB + s * B0_STG + row * 144 + ch * 16,
                      B + (size_t)(n0 + row) * ldb + k0 + ch * 8);
            }
        } else {
            #pragma unroll
            for (int p = 0; p < 4; p++) {
                int idx = tid + 256 * p;
                int krow = idx >> 4, kch = idx & 15;
                cpa16(BsB + s * B1_STG + krow * 272 + kch * 16,
                      B + (size_t)(k0 + krow) * ldb + n0 + kch * 8);
            }
        }
    };

    const int kt = K >> 6;   // BK = 64

    loadA(0, 0);  loadB(0, 0);  cp_commit();
    loadA(1, 64); loadB(1, 64); cp_commit();

    for (int it = 0; it < kt; it++) {
        const int s = it % 3;
        if (it == kt - 1) cp_wait<0>(); else cp_wait<1>();
        __syncthreads();

        // issue next slab FIRST (stage (it+2)%3 was fully consumed before this barrier)
        if (it + 2 < kt) {
            loadA((it + 2) % 3, (it + 2) * 64);
            loadB((it + 2) % 3, (it + 2) * 64);
            cp_commit();
        }

        #pragma unroll
        for (int kk = 0; kk < 4; kk++) {
            uint32_t a[4][4];
            #pragma unroll
            for (int mf = 0; mf < 4; mf++)
                ldsm4(a[mf][0], a[mf][1], a[mf][2], a[mf][3],
                      aBase + s * A_STG + mf * 2304 + kk * 32);
            uint32_t bf[4][2];
            #pragma unroll
            for (int nf2 = 0; nf2 < 2; nf2++) {
                uint32_t r0, r1, r2, r3;
                if (TRB == 0) {
                    ldsm4(r0, r1, r2, r3, bBase0 + s * B0_STG + nf2 * 2304 + kk * 32);
                } else {
                    ldsm4t(r0, r1, r2, r3, bBase1 + s * B1_STG + kk * 4352 + nf2 * 32);
                }
                bf[nf2 * 2][0] = r0; bf[nf2 * 2][1] = r1;
                bf[nf2 * 2 + 1][0] = r2; bf[nf2 * 2 + 1][1] = r3;
            }
            #pragma unroll
            for (int mf = 0; mf < 4; mf++)
                #pragma unroll
                for (int nf = 0; nf < 4; nf++)
                    mma_f16(c[mf][nf][0], c[mf][nf][1], c[mf][nf][2], c[mf][nf][3],
                            a[mf][0], a[mf][1], a[mf][2], a[mf][3],
                            bf[nf][0], bf[nf][1]);
        }
    }

    // ---------------- epilogue ----------------
    #pragma unroll
    for (int mf = 0; mf < 4; mf++) {
        const int r0 = m0 + wm * 64 + mf * 16 + g;
        const int r1 = r0 + 8;
        float add0 = 0.f, add1 = 0.f, mul0 = 1.f, mul1 = 1.f;
        if (EPI == 3) { add0 = bias[r0]; add1 = bias[r1]; }
        if (EPI == 2) {
            mul0 = 1.f / rowsum[z * NPIX + r0];
            mul1 = 1.f / rowsum[z * NPIX + r1];
        }
        float rsum0 = 0.f, rsum1 = 0.f;
        #pragma unroll
        for (int nf = 0; nf < 4; nf++) {
            const int cc = n0 + wn * 32 + nf * 8 + 2 * tr;
            float v0 = c[mf][nf][0], v1 = c[mf][nf][1];
            float v2 = c[mf][nf][2], v3 = c[mf][nf][3];
            if (EPI == 0) {
                v0 += bias[cc]; v1 += bias[cc + 1];
                v2 += bias[cc]; v3 += bias[cc + 1];
            }
            if (EPI == 1) {
                v0 = __expf(v0 * alpha); v1 = __expf(v1 * alpha);
                v2 = __expf(v2 * alpha); v3 = __expf(v3 * alpha);
                rsum0 += v0 + v1; rsum1 += v2 + v3;
            }
            if (EPI == 2) { v0 *= mul0; v1 *= mul0; v2 *= mul1; v3 *= mul1; }
            if (EPI != 3) {
                __half* Ch = (__half*)Cv + (size_t)z * sC;
                *(__half2*)&Ch[(size_t)r0 * ldc + cc] = __floats2half2_rn(v0, v1);
                *(__half2*)&Ch[(size_t)r1 * ldc + cc] = __floats2half2_rn(v2, v3);
            } else {
                float* Cf = (float*)Cv + (size_t)z * sC;
                const float* Rp = resid + (size_t)z * sR;
                float2 o0 = make_float2(v0 + add0 + Rp[(size_t)r0 * ldc + cc],
                                        v1 + add0 + Rp[(size_t)r0 * ldc + cc + 1]);
                float2 o1 = make_float2(v2 + add1 + Rp[(size_t)r1 * ldc + cc],
                                        v3 + add1 + Rp[(size_t)r1 * ldc + cc + 1]);
                *(float2*)&Cf[(size_t)r0 * ldc + cc] = o0;
                *(float2*)&Cf[(size_t)r1 * ldc + cc] = o1;
            }
        }
        if (EPI == 1) {
            rsum0 += __shfl_xor_sync(0xffffffffu, rsum0, 1);
            rsum0 += __shfl_xor_sync(0xffffffffu, rsum0, 2);
            rsum1 += __shfl_xor_sync(0xffffffffu, rsum1, 1);
            rsum1 += __shfl_xor_sync(0xffffffffu, rsum1, 2);
            if (tr == 0) {
                atomicAdd(&rowsum[z * NPIX + r0], rsum0);
                atomicAdd(&rowsum[z * NPIX + r1], rsum1);
            }
        }
    }
}

// ---------------- launch ----------------
extern "C" void kernel_launch(void* const* d_in, const int* in_sizes, int n_in,
                              void* d_out, int out_size)
{
    const float* x      = (const float*)d_in[0];
    const float* gamma  = (const float*)d_in[1];
    const float* beta   = (const float*)d_in[2];
    const float* w_qkv  = (const float*)d_in[3];
    const float* b_qkv  = (const float*)d_in[4];
    const float* w_proj = (const float*)d_in[5];
    const float* b_proj = (const float*)d_in[6];
    float* out = (float*)d_out;

    __half *xnT, *qkT, *E, *O, *wq, *wp;
    float* rs;
    cudaGetSymbolAddress((void**)&xnT, g_xnT);
    cudaGetSymbolAddress((void**)&qkT, g_qkT);
    cudaGetSymbolAddress((void**)&E,   g_E);
    cudaGetSymbolAddress((void**)&O,   g_O);
    cudaGetSymbolAddress((void**)&wq,  g_wq);
    cudaGetSymbolAddress((void**)&wp,  g_wp);
    cudaGetSymbolAddress((void**)&rs,  g_rs);

    cudaFuncSetAttribute(gemm_h<0,0>, cudaFuncAttributeMaxDynamicSharedMemorySize, SMEM_SZ);
    cudaFuncSetAttribute(gemm_h<1,0>, cudaFuncAttributeMaxDynamicSharedMemorySize, SMEM_SZ);
    cudaFuncSetAttribute(gemm_h<2,1>, cudaFuncAttributeMaxDynamicSharedMemorySize, SMEM_SZ);
    cudaFuncSetAttribute(gemm_h<3,0>, cudaFuncAttributeMaxDynamicSharedMemorySize, SMEM_SZ);

    // 1) GroupNorm (+weights->fp16, rowsum=0)
    groupnorm_k<<<BATCH * 8, 256>>>(x, gamma, beta, xnT, w_qkv, w_proj, wq, wp, rs);

    // 2) QKV: qkT[n][o] = sum_c xnT[n,c]*Wqkv[o,c] + b[o]
    gemm_h<0,0><<<dim3(768 / 128, NPIX / 128, BATCH), 256, SMEM_SZ>>>(
        xnT, wq, qkT, CCH, CCH, CCH, 768,
        (long)NPIX * CCH, 0L, (long)NPIX * 768,
        b_qkv, nullptr, 0L, nullptr, 0.f);

    // 3) scores+exp+rowsum: E[n,m] = exp((1/16) sum_c q[n,c]*k[m,c])
    gemm_h<1,0><<<dim3(NPIX / 128, NPIX / 128, BATCH), 256, SMEM_SZ>>>(
        qkT, qkT + CCH, E, CCH, 768, 768, NPIX,
        (long)NPIX * 768, (long)NPIX * 768, (long)NPIX * NPIX,
        nullptr, nullptr, 0L, rs, 0.0625f);

    // 4) AV + normalize: O[n,c] = (sum_m E[n,m]*V[m,c]) / rowsum[n]
    gemm_h<2,1><<<dim3(CCH / 128, NPIX / 128, BATCH), 256, SMEM_SZ>>>(
        E, qkT + 512, O, NPIX, NPIX, 768, CCH,
        (long)NPIX * NPIX, (long)NPIX * 768, (long)NPIX * CCH,
        nullptr, nullptr, 0L, rs, 1.f);

    // 5) proj + bias + residual
    gemm_h<3,0><<<dim3(NPIX / 128, CCH / 128, BATCH), 256, SMEM_SZ>>>(
        wp, O, out, CCH, CCH, CCH, NPIX,
        0L, (long)NPIX * CCH, (long)CCH * NPIX,
        b_proj, x, (long)CCH * NPIX, nullptr, 1.f);
}

// round 15
// speedup vs baseline: 1.0638x; 1.0129x over previous
#include <cuda_runtime.h>
#include <cuda_fp16.h>
#include <cstdint>

#define BATCH 16
#define CCH   256
#define NPIX  1024

// ---------------- scratch (static device globals; no allocation) ----------------
__device__ __align__(128) __half g_xnT[BATCH * NPIX * CCH];           //  8 MB [b][n][c]
__device__ __align__(128) __half g_qkT[BATCH * NPIX * 3 * CCH];       // 24 MB [b][n][o] q|k|v
__device__ __align__(128) __half g_E  [(size_t)BATCH * NPIX * NPIX];  // 32 MB [b][n][m]
__device__ __align__(128) __half g_O  [BATCH * NPIX * CCH];           //  8 MB [b][n][c]
__device__ __align__(128) float  g_rs [BATCH * NPIX];
__device__ __align__(128) __half g_wq [3 * CCH * CCH];
__device__ __align__(128) __half g_wp [CCH * CCH];

// ---------------- helpers ----------------
__device__ __forceinline__ void cpa16(uint32_t dst, const void* src) {
    asm volatile("cp.async.cg.shared.global [%0], [%1], 16;" :: "r"(dst), "l"(src));
}
__device__ __forceinline__ void cp_commit() { asm volatile("cp.async.commit_group;"); }
template<int N> __device__ __forceinline__ void cp_wait() { asm volatile("cp.async.wait_group %0;" :: "n"(N)); }

__device__ __forceinline__ void mma_f16(float& c0, float& c1, float& c2, float& c3,
                                        uint32_t a0, uint32_t a1, uint32_t a2, uint32_t a3,
                                        uint32_t b0, uint32_t b1) {
    asm volatile(
        "mma.sync.aligned.m16n8k16.row.col.f32.f16.f16.f32 "
        "{%0,%1,%2,%3}, {%4,%5,%6,%7}, {%8,%9}, {%0,%1,%2,%3};"
        : "+f"(c0), "+f"(c1), "+f"(c2), "+f"(c3)
        : "r"(a0), "r"(a1), "r"(a2), "r"(a3), "r"(b0), "r"(b1));
}
__device__ __forceinline__ void ldsm4(uint32_t& r0, uint32_t& r1, uint32_t& r2, uint32_t& r3, uint32_t a) {
    asm volatile("ldmatrix.sync.aligned.m8n8.x4.shared.b16 {%0,%1,%2,%3}, [%4];"
        : "=r"(r0), "=r"(r1), "=r"(r2), "=r"(r3) : "r"(a));
}
__device__ __forceinline__ void ldsm4t(uint32_t& r0, uint32_t& r1, uint32_t& r2, uint32_t& r3, uint32_t a) {
    asm volatile("ldmatrix.sync.aligned.m8n8.x4.trans.shared.b16 {%0,%1,%2,%3}, [%4];"
        : "=r"(r0), "=r"(r1), "=r"(r2), "=r"(r3) : "r"(a));
}

// ---------------- GroupNorm (+ fused weight convert + rowsum zero) ----------------
__global__ void groupnorm_k(const float* __restrict__ x, const float* __restrict__ gamma,
                            const float* __restrict__ beta, __half* __restrict__ xnT,
                            const float* __restrict__ wqf, const float* __restrict__ wpf,
                            __half* __restrict__ owq, __half* __restrict__ owp,
                            float* __restrict__ rs)
{
    __shared__ float smT[32][65];
    __shared__ float red0[8], red1[8];
    const int bg = blockIdx.x, b = bg >> 3, g = bg & 7;
    const float* xp = x + (size_t)bg * 32768;
    const int tid = threadIdx.x, lane = tid & 31, warp = tid >> 5;

    // fused prep (grid-strided over all 128*256 = 32768 threads)
    {
        int gi = bg * 256 + tid;
        #pragma unroll
        for (int j = 0; j < 6; j++) {
            int idx = gi + 32768 * j;
            if (idx < 3 * CCH * CCH) owq[idx] = __float2half(wqf[idx]);
        }
        #pragma unroll
        for (int j = 0; j < 2; j++) {
            int idx = gi + 32768 * j;
            if (idx < CCH * CCH) owp[idx] = __float2half(wpf[idx]);
        }
        if (gi < BATCH * NPIX) rs[gi] = 0.f;
    }

    float s = 0.f, s2 = 0.f;
    for (int i = tid; i < 32768; i += 256) { float v = xp[i]; s += v; s2 += v * v; }
    #pragma unroll
    for (int o = 16; o > 0; o >>= 1) {
        s  += __shfl_xor_sync(0xffffffffu, s,  o);
        s2 += __shfl_xor_sync(0xffffffffu, s2, o);
    }
    if (lane == 0) { red0[warp] = s; red1[warp] = s2; }
    __syncthreads();
    if (warp == 0) {
        s  = (lane < 8) ? red0[lane] : 0.f;
        s2 = (lane < 8) ? red1[lane] : 0.f;
        #pragma unroll
        for (int o = 4; o > 0; o >>= 1) {
            s  += __shfl_xor_sync(0xffffffffu, s,  o);
            s2 += __shfl_xor_sync(0xffffffffu, s2, o);
        }
        if (lane == 0) { red0[0] = s; red1[0] = s2; }
    }
    __syncthreads();
    float mean = red0[0] * (1.f / 32768.f);
    float var  = red1[0] * (1.f / 32768.f) - mean * mean;
    float rstd = rsqrtf(var + 1e-5f);

    const int p = tid >> 2, cq = (tid & 3) * 8;
    float gm[8], bt[8];
    #pragma unroll
    for (int j = 0; j < 8; j++) {
        float gj = gamma[g * 32 + cq + j] * rstd;
        gm[j] = gj;
        bt[j] = beta[g * 32 + cq + j] - mean * gj;
    }
    for (int tp = 0; tp < 1024; tp += 64) {
        __syncthreads();
        #pragma unroll
        for (int i = 0; i < 8; i++) {
            int idx = tid + 256 * i;
            int c = idx >> 6, pp = idx & 63;
            smT[c][pp] = xp[c * 1024 + tp + pp];
        }
        __syncthreads();
        uint32_t pk[4];
        #pragma unroll
        for (int j = 0; j < 4; j++) {
            float v0 = smT[cq + 2 * j][p]     * gm[2 * j]     + bt[2 * j];
            float v1 = smT[cq + 2 * j + 1][p] * gm[2 * j + 1] + bt[2 * j + 1];
            __half2 h = __floats2half2_rn(v0, v1);
            pk[j] = *(uint32_t*)&h;
        }
        *(uint4*)&xnT[((size_t)b * NPIX + tp + p) * CCH + g * 32 + cq] = *(uint4*)pk;
    }
}

// ---------------- FP16 tensor-core GEMM, CTA 128x128, warp 64x32, BK=64, 3-stage ----------------
// D[m,n] = sum_k A[m,k] * B(n,k)   (TRB=0: B row-n k-major, stride ldb)
//                                  (TRB=1: B stored [k][n], row stride ldb)
// EPI: 0 = +bias[col] -> fp16 ; 1 = exp(alpha*d)+rowsum atomic -> fp16 ;
//      2 = d/rowsum[row] -> fp16 ; 3 = d + bias[row] + resid -> fp32
// 256 threads (8 warps 2x4), BK=64, 3-stage cp.async ring, ONE barrier per slab,
// next-slab loads issued after the MMA block (R11 ordering — R14 showed early issue regresses).
#define A_STG  18432   // 128 rows * 144 B
#define B0_STG 18432
#define B1_STG 17408   // 64 rows * 272 B
#define B_OFF  55296   // 3 * A_STG
#define SMEM_SZ (B_OFF + 3 * B0_STG)   // 110592 B

template<int EPI, int TRB>
__global__ void __launch_bounds__(256, 2)
gemm_h(const __half* __restrict__ A, const __half* __restrict__ B,
       void* __restrict__ Cv, int K, int lda, int ldb, int ldc,
       long sA, long sB, long sC,
       const float* __restrict__ bias, const float* __restrict__ resid, long sR,
       float* __restrict__ rowsum, float alpha)
{
    extern __shared__ char dsh[];
    const uint32_t sb = (uint32_t)__cvta_generic_to_shared(dsh);
    const uint32_t AsB = sb;
    const uint32_t BsB = sb + B_OFF;

    const int z = blockIdx.z;
    A += (size_t)z * sA;
    B += (size_t)z * sB;

    const int m0 = blockIdx.y * 128, n0 = blockIdx.x * 128;
    const int tid = threadIdx.x, lane = tid & 31, wid = tid >> 5;
    const int wm = wid & 1, wn = wid >> 1;   // 2 x 4 warps, warp tile 64x32
    const int g = lane >> 2, tr = lane & 3;

    const int a_row = (lane & 7) | (((lane >> 3) & 1) << 3);
    const int a_hi4 = (lane >= 16) ? 4 : 0;
    const int b_row = (lane & 7) + ((lane >= 16) ? 8 : 0);
    const int b_hi4 = ((lane >> 3) & 1) ? 4 : 0;
    const int t_row = lane & 15, t_col = (lane >> 4) * 8;

    const uint32_t aBase  = AsB + (uint32_t)((wm * 64 + a_row) * 144 + a_hi4 * 4);
    const uint32_t bBase0 = BsB + (uint32_t)((wn * 32 + b_row) * 144 + b_hi4 * 4);
    const uint32_t bBase1 = BsB + (uint32_t)(t_row * 272 + (wn * 32 + t_col) * 2);

    float c[4][4][4];
    #pragma unroll
    for (int i = 0; i < 4; i++)
        #pragma unroll
        for (int j = 0; j < 4; j++)
            #pragma unroll
            for (int t = 0; t < 4; t++) c[i][j][t] = 0.f;

    auto loadA = [&](int s, int k0) {
        #pragma unroll
        for (int p = 0; p < 4; p++) {
            int idx = tid + 256 * p;
            int row = idx >> 3, ch = idx & 7;
            cpa16(AsB + s * A_STG + row * 144 + ch * 16,
                  A + (size_t)(m0 + row) * lda + k0 + ch * 8);
        }
    };
    auto loadB = [&](int s, int k0) {
        if (TRB == 0) {
            #pragma unroll
            for (int p = 0; p < 4; p++) {
                int idx = tid + 256 * p;
                int row = idx >> 3, ch = idx & 7;
                cpa16(BsB + s * B0_STG + row * 144 + ch * 16,
                      B + (size_t)(n0 + row) * ldb + k0 + ch * 8);
            }
        } else {
            #pragma unroll
            for (int p = 0; p < 4; p++) {
                int idx = tid + 256 * p;
                int krow = idx >> 4, kch = idx & 15;
                cpa16(BsB + s * B1_STG + krow * 272 + kch * 16,
                      B + (size_t)(k0 + krow) * ldb + n0 + kch * 8);
            }
        }
    };

    const int kt = K >> 6;   // BK = 64

    loadA(0, 0);  loadB(0, 0);  cp_commit();
    loadA(1, 64); loadB(1, 64); cp_commit();

    for (int it = 0; it < kt; it++) {
        const int s = it % 3;
        if (it == kt - 1) cp_wait<0>(); else cp_wait<1>();
        __syncthreads();

        #pragma unroll
        for (int kk = 0; kk < 4; kk++) {
            uint32_t a[4][4];
            #pragma unroll
            for (int mf = 0; mf < 4; mf++)
                ldsm4(a[mf][0], a[mf][1], a[mf][2], a[mf][3],
                      aBase + s * A_STG + mf * 2304 + kk * 32);
            uint32_t bf[4][2];
            #pragma unroll
            for (int nf2 = 0; nf2 < 2; nf2++) {
                uint32_t r0, r1, r2, r3;
                if (TRB == 0) {
                    ldsm4(r0, r1, r2, r3, bBase0 + s * B0_STG + nf2 * 2304 + kk * 32);
                } else {
                    ldsm4t(r0, r1, r2, r3, bBase1 + s * B1_STG + kk * 4352 + nf2 * 32);
                }
                bf[nf2 * 2][0] = r0; bf[nf2 * 2][1] = r1;
                bf[nf2 * 2 + 1][0] = r2; bf[nf2 * 2 + 1][1] = r3;
            }
            #pragma unroll
            for (int mf = 0; mf < 4; mf++)
                #pragma unroll
                for (int nf = 0; nf < 4; nf++)
                    mma_f16(c[mf][nf][0], c[mf][nf][1], c[mf][nf][2], c[mf][nf][3],
                            a[mf][0], a[mf][1], a[mf][2], a[mf][3],
                            bf[nf][0], bf[nf][1]);
        }
        if (it + 2 < kt) {
            loadA((it + 2) % 3, (it + 2) * 64);
            loadB((it + 2) % 3, (it + 2) * 64);
            cp_commit();
        }
    }

    // ---------------- epilogue ----------------
    #pragma unroll
    for (int mf = 0; mf < 4; mf++) {
        const int r0 = m0 + wm * 64 + mf * 16 + g;
        const int r1 = r0 + 8;
        float add0 = 0.f, add1 = 0.f, mul0 = 1.f, mul1 = 1.f;
        if (EPI == 3) { add0 = bias[r0]; add1 = bias[r1]; }
        if (EPI == 2) {
            mul0 = 1.f / rowsum[z * NPIX + r0];
            mul1 = 1.f / rowsum[z * NPIX + r1];
        }
        float rsum0 = 0.f, rsum1 = 0.f;
        #pragma unroll
        for (int nf = 0; nf < 4; nf++) {
            const int cc = n0 + wn * 32 + nf * 8 + 2 * tr;
            float v0 = c[mf][nf][0], v1 = c[mf][nf][1];
            float v2 = c[mf][nf][2], v3 = c[mf][nf][3];
            if (EPI == 0) {
                v0 += bias[cc]; v1 += bias[cc + 1];
                v2 += bias[cc]; v3 += bias[cc + 1];
            }
            if (EPI == 1) {
                v0 = __expf(v0 * alpha); v1 = __expf(v1 * alpha);
                v2 = __expf(v2 * alpha); v3 = __expf(v3 * alpha);
                rsum0 += v0 + v1; rsum1 += v2 + v3;
            }
            if (EPI == 2) { v0 *= mul0; v1 *= mul0; v2 *= mul1; v3 *= mul1; }
            if (EPI != 3) {
                __half* Ch = (__half*)Cv + (size_t)z * sC;
                *(__half2*)&Ch[(size_t)r0 * ldc + cc] = __floats2half2_rn(v0, v1);
                *(__half2*)&Ch[(size_t)r1 * ldc + cc] = __floats2half2_rn(v2, v3);
            } else {
                float* Cf = (float*)Cv + (size_t)z * sC;
                const float* Rp = resid + (size_t)z * sR;
                float2 o0 = make_float2(v0 + add0 + Rp[(size_t)r0 * ldc + cc],
                                        v1 + add0 + Rp[(size_t)r0 * ldc + cc + 1]);
                float2 o1 = make_float2(v2 + add1 + Rp[(size_t)r1 * ldc + cc],
                                        v3 + add1 + Rp[(size_t)r1 * ldc + cc + 1]);
                *(float2*)&Cf[(size_t)r0 * ldc + cc] = o0;
                *(float2*)&Cf[(size_t)r1 * ldc + cc] = o1;
            }
        }
        if (EPI == 1) {
            rsum0 += __shfl_xor_sync(0xffffffffu, rsum0, 1);
            rsum0 += __shfl_xor_sync(0xffffffffu, rsum0, 2);
            rsum1 += __shfl_xor_sync(0xffffffffu, rsum1, 1);
            rsum1 += __shfl_xor_sync(0xffffffffu, rsum1, 2);
            if (tr == 0) {
                atomicAdd(&rowsum[z * NPIX + r0], rsum0);
                atomicAdd(&rowsum[z * NPIX + r1], rsum1);
            }
        }
    }
}

// ---------------- launch ----------------
extern "C" void kernel_launch(void* const* d_in, const int* in_sizes, int n_in,
                              void* d_out, int out_size)
{
    const float* x      = (const float*)d_in[0];
    const float* gamma  = (const float*)d_in[1];
    const float* beta   = (const float*)d_in[2];
    const float* w_qkv  = (const float*)d_in[3];
    const float* b_qkv  = (const float*)d_in[4];
    const float* w_proj = (const float*)d_in[5];
    const float* b_proj = (const float*)d_in[6];
    float* out = (float*)d_out;

    __half *xnT, *qkT, *E, *O, *wq, *wp;
    float* rs;
    cudaGetSymbolAddress((void**)&xnT, g_xnT);
    cudaGetSymbolAddress((void**)&qkT, g_qkT);
    cudaGetSymbolAddress((void**)&E,   g_E);
    cudaGetSymbolAddress((void**)&O,   g_O);
    cudaGetSymbolAddress((void**)&wq,  g_wq);
    cudaGetSymbolAddress((void**)&wp,  g_wp);
    cudaGetSymbolAddress((void**)&rs,  g_rs);

    cudaFuncSetAttribute(gemm_h<0,0>, cudaFuncAttributeMaxDynamicSharedMemorySize, SMEM_SZ);
    cudaFuncSetAttribute(gemm_h<1,0>, cudaFuncAttributeMaxDynamicSharedMemorySize, SMEM_SZ);
    cudaFuncSetAttribute(gemm_h<2,1>, cudaFuncAttributeMaxDynamicSharedMemorySize, SMEM_SZ);
    cudaFuncSetAttribute(gemm_h<3,0>, cudaFuncAttributeMaxDynamicSharedMemorySize, SMEM_SZ);

    // 1) GroupNorm (+weights->fp16, rowsum=0)
    groupnorm_k<<<BATCH * 8, 256>>>(x, gamma, beta, xnT, w_qkv, w_proj, wq, wp, rs);

    // 2) QKV: qkT[n][o] = sum_c xnT[n,c]*Wqkv[o,c] + b[o]
    gemm_h<0,0><<<dim3(768 / 128, NPIX / 128, BATCH), 256, SMEM_SZ>>>(
        xnT, wq, qkT, CCH, CCH, CCH, 768,
        (long)NPIX * CCH, 0L, (long)NPIX * 768,
        b_qkv, nullptr, 0L, nullptr, 0.f);

    // 3) scores+exp+rowsum: E[n,m] = exp((1/16) sum_c q[n,c]*k[m,c])
    gemm_h<1,0><<<dim3(NPIX / 128, NPIX / 128, BATCH), 256, SMEM_SZ>>>(
        qkT, qkT + CCH, E, CCH, 768, 768, NPIX,
        (long)NPIX * 768, (long)NPIX * 768, (long)NPIX * NPIX,
        nullptr, nullptr, 0L, rs, 0.0625f);

    // 4) AV + normalize: O[n,c] = (sum_m E[n,m]*V[m,c]) / rowsum[n]
    gemm_h<2,1><<<dim3(CCH / 128, NPIX / 128, BATCH), 256, SMEM_SZ>>>(
        E, qkT + 512, O, NPIX, NPIX, 768, CCH,
        (long)NPIX * NPIX, (long)NPIX * 768, (long)NPIX * CCH,
        nullptr, nullptr, 0L, rs, 1.f);

    // 5) proj + bias + residual
    gemm_h<3,0><<<dim3(NPIX / 128, CCH / 128, BATCH), 256, SMEM_SZ>>>(
        wp, O, out, CCH, CCH, CCH, NPIX,
        0L, (long)NPIX * CCH, (long)CCH * NPIX,
        b_proj, x, (long)CCH * NPIX, nullptr, 1.f);
}

// round 16
// speedup vs baseline: 1.0825x; 1.0176x over previous
#include <cuda_runtime.h>
#include <cuda_fp16.h>
#include <cstdint>

#define BATCH 16
#define CCH   256
#define NPIX  1024

// ---------------- scratch (static device globals; no allocation) ----------------
__device__ __align__(128) __half g_xnT[BATCH * NPIX * CCH];           //  8 MB [b][n][c]
__device__ __align__(128) __half g_qkT[BATCH * NPIX * 3 * CCH];       // 24 MB [b][n][o] q|k|v
__device__ __align__(128) __half g_E  [(size_t)BATCH * NPIX * NPIX];  // 32 MB [b][n][m]
__device__ __align__(128) __half g_O  [BATCH * NPIX * CCH];           //  8 MB [b][n][c]
__device__ __align__(128) float  g_rs [BATCH * NPIX];
__device__ __align__(128) __half g_wq [3 * CCH * CCH];
__device__ __align__(128) __half g_wp [CCH * CCH];

// ---------------- helpers ----------------
__device__ __forceinline__ void cpa16(uint32_t dst, const void* src) {
    asm volatile("cp.async.cg.shared.global [%0], [%1], 16;" :: "r"(dst), "l"(src));
}
__device__ __forceinline__ void cp_commit() { asm volatile("cp.async.commit_group;"); }
template<int N> __device__ __forceinline__ void cp_wait() { asm volatile("cp.async.wait_group %0;" :: "n"(N)); }

__device__ __forceinline__ void mma_f16(float& c0, float& c1, float& c2, float& c3,
                                        uint32_t a0, uint32_t a1, uint32_t a2, uint32_t a3,
                                        uint32_t b0, uint32_t b1) {
    asm volatile(
        "mma.sync.aligned.m16n8k16.row.col.f32.f16.f16.f32 "
        "{%0,%1,%2,%3}, {%4,%5,%6,%7}, {%8,%9}, {%0,%1,%2,%3};"
        : "+f"(c0), "+f"(c1), "+f"(c2), "+f"(c3)
        : "r"(a0), "r"(a1), "r"(a2), "r"(a3), "r"(b0), "r"(b1));
}
__device__ __forceinline__ void ldsm4(uint32_t& r0, uint32_t& r1, uint32_t& r2, uint32_t& r3, uint32_t a) {
    asm volatile("ldmatrix.sync.aligned.m8n8.x4.shared.b16 {%0,%1,%2,%3}, [%4];"
        : "=r"(r0), "=r"(r1), "=r"(r2), "=r"(r3) : "r"(a));
}
__device__ __forceinline__ void ldsm4t(uint32_t& r0, uint32_t& r1, uint32_t& r2, uint32_t& r3, uint32_t a) {
    asm volatile("ldmatrix.sync.aligned.m8n8.x4.trans.shared.b16 {%0,%1,%2,%3}, [%4];"
        : "=r"(r0), "=r"(r1), "=r"(r2), "=r"(r3) : "r"(a));
}

// ---------------- GroupNorm (+ fused weight convert + rowsum zero), vectorized ----------------
__global__ void groupnorm_k(const float* __restrict__ x, const float* __restrict__ gamma,
                            const float* __restrict__ beta, __half* __restrict__ xnT,
                            const float* __restrict__ wqf, const float* __restrict__ wpf,
                            __half* __restrict__ owq, __half* __restrict__ owp,
                            float* __restrict__ rs)
{
    __shared__ float smT[32][65];
    __shared__ float red0[8], red1[8];
    const int bg = blockIdx.x, b = bg >> 3, g = bg & 7;
    const float* xp = x + (size_t)bg * 32768;
    const int tid = threadIdx.x, lane = tid & 31, warp = tid >> 5;

    // fused prep (grid-strided over all 128*256 = 32768 threads)
    {
        int gi = bg * 256 + tid;
        #pragma unroll
        for (int j = 0; j < 6; j++) {
            int idx = gi + 32768 * j;
            if (idx < 3 * CCH * CCH) owq[idx] = __float2half(wqf[idx]);
        }
        #pragma unroll
        for (int j = 0; j < 2; j++) {
            int idx = gi + 32768 * j;
            if (idx < CCH * CCH) owp[idx] = __float2half(wpf[idx]);
        }
        if (gi < BATCH * NPIX) rs[gi] = 0.f;
    }

    // stats pass: float4 loads (32768 floats = 8192 float4 / 256 threads = 32 each)
    float s = 0.f, s2 = 0.f;
    {
        const float4* xp4 = (const float4*)xp;
        #pragma unroll 4
        for (int i = tid; i < 8192; i += 256) {
            float4 v = xp4[i];
            s  += v.x + v.y + v.z + v.w;
            s2 += v.x * v.x + v.y * v.y + v.z * v.z + v.w * v.w;
        }
    }
    #pragma unroll
    for (int o = 16; o > 0; o >>= 1) {
        s  += __shfl_xor_sync(0xffffffffu, s,  o);
        s2 += __shfl_xor_sync(0xffffffffu, s2, o);
    }
    if (lane == 0) { red0[warp] = s; red1[warp] = s2; }
    __syncthreads();
    if (warp == 0) {
        s  = (lane < 8) ? red0[lane] : 0.f;
        s2 = (lane < 8) ? red1[lane] : 0.f;
        #pragma unroll
        for (int o = 4; o > 0; o >>= 1) {
            s  += __shfl_xor_sync(0xffffffffu, s,  o);
            s2 += __shfl_xor_sync(0xffffffffu, s2, o);
        }
        if (lane == 0) { red0[0] = s; red1[0] = s2; }
    }
    __syncthreads();
    float mean = red0[0] * (1.f / 32768.f);
    float var  = red1[0] * (1.f / 32768.f) - mean * mean;
    float rstd = rsqrtf(var + 1e-5f);

    const int p = tid >> 2, cq = (tid & 3) * 8;
    float gm[8], bt[8];
    #pragma unroll
    for (int j = 0; j < 8; j++) {
        float gj = gamma[g * 32 + cq + j] * rstd;
        gm[j] = gj;
        bt[j] = beta[g * 32 + cq + j] - mean * gj;
    }
    // transpose/normalize pass: staging loads via float4 (2048 floats/stage / 256 thr = 2 float4 each)
    const int sc = tid >> 3, sp0 = (tid & 7) * 8;
    for (int tp = 0; tp < 1024; tp += 64) {
        __syncthreads();
        {
            float4 v0 = *(const float4*)&xp[sc * 1024 + tp + sp0];
            float4 v1 = *(const float4*)&xp[sc * 1024 + tp + sp0 + 4];
            smT[sc][sp0 + 0] = v0.x; smT[sc][sp0 + 1] = v0.y;
            smT[sc][sp0 + 2] = v0.z; smT[sc][sp0 + 3] = v0.w;
            smT[sc][sp0 + 4] = v1.x; smT[sc][sp0 + 5] = v1.y;
            smT[sc][sp0 + 6] = v1.z; smT[sc][sp0 + 7] = v1.w;
        }
        __syncthreads();
        uint32_t pk[4];
        #pragma unroll
        for (int j = 0; j < 4; j++) {
            float v0 = smT[cq + 2 * j][p]     * gm[2 * j]     + bt[2 * j];
            float v1 = smT[cq + 2 * j + 1][p] * gm[2 * j + 1] + bt[2 * j + 1];
            __half2 h = __floats2half2_rn(v0, v1);
            pk[j] = *(uint32_t*)&h;
        }
        *(uint4*)&xnT[((size_t)b * NPIX + tp + p) * CCH + g * 32 + cq] = *(uint4*)pk;
    }
}

// ---------------- FP16 tensor-core GEMM, CTA 128x128, warp 64x32, BK=64, 3-stage ----------------
// D[m,n] = sum_k A[m,k] * B(n,k)   (TRB=0: B row-n k-major, stride ldb)
//                                  (TRB=1: B stored [k][n], row stride ldb)
// EPI: 0 = +bias[col] -> fp16 ; 1 = exp(alpha*d)+rowsum atomic -> fp16 ;
//      2 = d/rowsum[row] -> fp16 ; 3 = d + bias[row] + resid -> fp32
// 256 threads (8 warps 2x4), BK=64, 3-stage cp.async ring, ONE barrier per slab,
// next-slab loads issued after the MMA block (R11 ordering).
#define A_STG  18432   // 128 rows * 144 B
#define B0_STG 18432
#define B1_STG 17408   // 64 rows * 272 B
#define B_OFF  55296   // 3 * A_STG
#define SMEM_SZ (B_OFF + 3 * B0_STG)   // 110592 B

template<int EPI, int TRB>
__global__ void __launch_bounds__(256, 2)
gemm_h(const __half* __restrict__ A, const __half* __restrict__ B,
       void* __restrict__ Cv, int K, int lda, int ldb, int ldc,
       long sA, long sB, long sC,
       const float* __restrict__ bias, const float* __restrict__ resid, long sR,
       float* __restrict__ rowsum, float alpha)
{
    extern __shared__ char dsh[];
    const uint32_t sb = (uint32_t)__cvta_generic_to_shared(dsh);
    const uint32_t AsB = sb;
    const uint32_t BsB = sb + B_OFF;

    const int z = blockIdx.z;
    A += (size_t)z * sA;
    B += (size_t)z * sB;

    const int m0 = blockIdx.y * 128, n0 = blockIdx.x * 128;
    const int tid = threadIdx.x, lane = tid & 31, wid = tid >> 5;
    const int wm = wid & 1, wn = wid >> 1;   // 2 x 4 warps, warp tile 64x32
    const int g = lane >> 2, tr = lane & 3;

    const int a_row = (lane & 7) | (((lane >> 3) & 1) << 3);
    const int a_hi4 = (lane >= 16) ? 4 : 0;
    const int b_row = (lane & 7) + ((lane >= 16) ? 8 : 0);
    const int b_hi4 = ((lane >> 3) & 1) ? 4 : 0;
    const int t_row = lane & 15, t_col = (lane >> 4) * 8;

    const uint32_t aBase  = AsB + (uint32_t)((wm * 64 + a_row) * 144 + a_hi4 * 4);
    const uint32_t bBase0 = BsB + (uint32_t)((wn * 32 + b_row) * 144 + b_hi4 * 4);
    const uint32_t bBase1 = BsB + (uint32_t)(t_row * 272 + (wn * 32 + t_col) * 2);

    float c[4][4][4];
    #pragma unroll
    for (int i = 0; i < 4; i++)
        #pragma unroll
        for (int j = 0; j < 4; j++)
            #pragma unroll
            for (int t = 0; t < 4; t++) c[i][j][t] = 0.f;

    auto loadA = [&](int s, int k0) {
        #pragma unroll
        for (int p = 0; p < 4; p++) {
            int idx = tid + 256 * p;
            int row = idx >> 3, ch = idx & 7;
            cpa16(AsB + s * A_STG + row * 144 + ch * 16,
                  A + (size_t)(m0 + row) * lda + k0 + ch * 8);
        }
    };
    auto loadB = [&](int s, int k0) {
        if (TRB == 0) {
            #pragma unroll
            for (int p = 0; p < 4; p++) {
                int idx = tid + 256 * p;
                int row = idx >> 3, ch = idx & 7;
                cpa16(BsB + s * B0_STG + row * 144 + ch * 16,
                      B + (size_t)(n0 + row) * ldb + k0 + ch * 8);
            }
        } else {
            #pragma unroll
            for (int p = 0; p < 4; p++) {
                int idx = tid + 256 * p;
                int krow = idx >> 4, kch = idx & 15;
                cpa16(BsB + s * B1_STG + krow * 272 + kch * 16,
                      B + (size_t)(k0 + krow) * ldb + n0 + kch * 8);
            }
        }
    };

    const int kt = K >> 6;   // BK = 64

    loadA(0, 0);  loadB(0, 0);  cp_commit();
    loadA(1, 64); loadB(1, 64); cp_commit();

    for (int it = 0; it < kt; it++) {
        const int s = it % 3;
        if (it == kt - 1) cp_wait<0>(); else cp_wait<1>();
        __syncthreads();

        #pragma unroll
        for (int kk = 0; kk < 4; kk++) {
            uint32_t a[4][4];
            #pragma unroll
            for (int mf = 0; mf < 4; mf++)
                ldsm4(a[mf][0], a[mf][1], a[mf][2], a[mf][3],
                      aBase + s * A_STG + mf * 2304 + kk * 32);
            uint32_t bf[4][2];
            #pragma unroll
            for (int nf2 = 0; nf2 < 2; nf2++) {
                uint32_t r0, r1, r2, r3;
                if (TRB == 0) {
                    ldsm4(r0, r1, r2, r3, bBase0 + s * B0_STG + nf2 * 2304 + kk * 32);
                } else {
                    ldsm4t(r0, r1, r2, r3, bBase1 + s * B1_STG + kk * 4352 + nf2 * 32);
                }
                bf[nf2 * 2][0] = r0; bf[nf2 * 2][1] = r1;
                bf[nf2 * 2 + 1][0] = r2; bf[nf2 * 2 + 1][1] = r3;
            }
            #pragma unroll
            for (int mf = 0; mf < 4; mf++)
                #pragma unroll
                for (int nf = 0; nf < 4; nf++)
                    mma_f16(c[mf][nf][0], c[mf][nf][1], c[mf][nf][2], c[mf][nf][3],
                            a[mf][0], a[mf][1], a[mf][2], a[mf][3],
                            bf[nf][0], bf[nf][1]);
        }
        if (it + 2 < kt) {
            loadA((it + 2) % 3, (it + 2) * 64);
            loadB((it + 2) % 3, (it + 2) * 64);
            cp_commit();
        }
    }

    // ---------------- epilogue ----------------
    #pragma unroll
    for (int mf = 0; mf < 4; mf++) {
        const int r0 = m0 + wm * 64 + mf * 16 + g;
        const int r1 = r0 + 8;
        float add0 = 0.f, add1 = 0.f, mul0 = 1.f, mul1 = 1.f;
        if (EPI == 3) { add0 = bias[r0]; add1 = bias[r1]; }
        if (EPI == 2) {
            mul0 = 1.f / rowsum[z * NPIX + r0];
            mul1 = 1.f / rowsum[z * NPIX + r1];
        }
        float rsum0 = 0.f, rsum1 = 0.f;
        #pragma unroll
        for (int nf = 0; nf < 4; nf++) {
            const int cc = n0 + wn * 32 + nf * 8 + 2 * tr;
            float v0 = c[mf][nf][0], v1 = c[mf][nf][1];
            float v2 = c[mf][nf][2], v3 = c[mf][nf][3];
            if (EPI == 0) {
                v0 += bias[cc]; v1 += bias[cc + 1];
                v2 += bias[cc]; v3 += bias[cc + 1];
            }
            if (EPI == 1) {
                v0 = __expf(v0 * alpha); v1 = __expf(v1 * alpha);
                v2 = __expf(v2 * alpha); v3 = __expf(v3 * alpha);
                rsum0 += v0 + v1; rsum1 += v2 + v3;
            }
            if (EPI == 2) { v0 *= mul0; v1 *= mul0; v2 *= mul1; v3 *= mul1; }
            if (EPI != 3) {
                __half* Ch = (__half*)Cv + (size_t)z * sC;
                *(__half2*)&Ch[(size_t)r0 * ldc + cc] = __floats2half2_rn(v0, v1);
                *(__half2*)&Ch[(size_t)r1 * ldc + cc] = __floats2half2_rn(v2, v3);
            } else {
                float* Cf = (float*)Cv + (size_t)z * sC;
                const float* Rp = resid + (size_t)z * sR;
                float2 o0 = make_float2(v0 + add0 + Rp[(size_t)r0 * ldc + cc],
                                        v1 + add0 + Rp[(size_t)r0 * ldc + cc + 1]);
                float2 o1 = make_float2(v2 + add1 + Rp[(size_t)r1 * ldc + cc],
                                        v3 + add1 + Rp[(size_t)r1 * ldc + cc + 1]);
                *(float2*)&Cf[(size_t)r0 * ldc + cc] = o0;
                *(float2*)&Cf[(size_t)r1 * ldc + cc] = o1;
            }
        }
        if (EPI == 1) {
            rsum0 += __shfl_xor_sync(0xffffffffu, rsum0, 1);
            rsum0 += __shfl_xor_sync(0xffffffffu, rsum0, 2);
            rsum1 += __shfl_xor_sync(0xffffffffu, rsum1, 1);
            rsum1 += __shfl_xor_sync(0xffffffffu, rsum1, 2);
            if (tr == 0) {
                atomicAdd(&rowsum[z * NPIX + r0], rsum0);
                atomicAdd(&rowsum[z * NPIX + r1], rsum1);
            }
        }
    }
}

// ---------------- launch ----------------
extern "C" void kernel_launch(void* const* d_in, const int* in_sizes, int n_in,
                              void* d_out, int out_size)
{
    const float* x      = (const float*)d_in[0];
    const float* gamma  = (const float*)d_in[1];
    const float* beta   = (const float*)d_in[2];
    const float* w_qkv  = (const float*)d_in[3];
    const float* b_qkv  = (const float*)d_in[4];
    const float* w_proj = (const float*)d_in[5];
    const float* b_proj = (const float*)d_in[6];
    float* out = (float*)d_out;

    __half *xnT, *qkT, *E, *O, *wq, *wp;
    float* rs;
    cudaGetSymbolAddress((void**)&xnT, g_xnT);
    cudaGetSymbolAddress((void**)&qkT, g_qkT);
    cudaGetSymbolAddress((void**)&E,   g_E);
    cudaGetSymbolAddress((void**)&O,   g_O);
    cudaGetSymbolAddress((void**)&wq,  g_wq);
    cudaGetSymbolAddress((void**)&wp,  g_wp);
    cudaGetSymbolAddress((void**)&rs,  g_rs);

    cudaFuncSetAttribute(gemm_h<0,0>, cudaFuncAttributeMaxDynamicSharedMemorySize, SMEM_SZ);
    cudaFuncSetAttribute(gemm_h<1,0>, cudaFuncAttributeMaxDynamicSharedMemorySize, SMEM_SZ);
    cudaFuncSetAttribute(gemm_h<2,1>, cudaFuncAttributeMaxDynamicSharedMemorySize, SMEM_SZ);
    cudaFuncSetAttribute(gemm_h<3,0>, cudaFuncAttributeMaxDynamicSharedMemorySize, SMEM_SZ);

    // 1) GroupNorm (+weights->fp16, rowsum=0)
    groupnorm_k<<<BATCH * 8, 256>>>(x, gamma, beta, xnT, w_qkv, w_proj, wq, wp, rs);

    // 2) QKV: qkT[n][o] = sum_c xnT[n,c]*Wqkv[o,c] + b[o]
    gemm_h<0,0><<<dim3(768 / 128, NPIX / 128, BATCH), 256, SMEM_SZ>>>(
        xnT, wq, qkT, CCH, CCH, CCH, 768,
        (long)NPIX * CCH, 0L, (long)NPIX * 768,
        b_qkv, nullptr, 0L, nullptr, 0.f);

    // 3) scores+exp+rowsum: E[n,m] = exp((1/16) sum_c q[n,c]*k[m,c])
    gemm_h<1,0><<<dim3(NPIX / 128, NPIX / 128, BATCH), 256, SMEM_SZ>>>(
        qkT, qkT + CCH, E, CCH, 768, 768, NPIX,
        (long)NPIX * 768, (long)NPIX * 768, (long)NPIX * NPIX,
        nullptr, nullptr, 0L, rs, 0.0625f);

    // 4) AV + normalize: O[n,c] = (sum_m E[n,m]*V[m,c]) / rowsum[n]
    gemm_h<2,1><<<dim3(CCH / 128, NPIX / 128, BATCH), 256, SMEM_SZ>>>(
        E, qkT + 512, O, NPIX, NPIX, 768, CCH,
        (long)NPIX * NPIX, (long)NPIX * 768, (long)NPIX * CCH,
        nullptr, nullptr, 0L, rs, 1.f);

    // 5) proj + bias + residual
    gemm_h<3,0><<<dim3(NPIX / 128, CCH / 128, BATCH), 256, SMEM_SZ>>>(
        wp, O, out, CCH, CCH, CCH, NPIX,
        0L, (long)NPIX * CCH, (long)CCH * NPIX,
        b_proj, x, (long)CCH * NPIX, nullptr, 1.f);
}